// round 11
// baseline (speedup 1.0000x reference)
#include <cuda_runtime.h>
#include <cuda_bf16.h>
#include <cuda_fp16.h>
#include <cfloat>
#include <cstdint>

#define N_ROWS 16384
#define DIM_IN 1024
#define DIM_H  512
#define MEM_M  8192
#define RATE   0.5f
#define SCORE_BIAS   512.0f
#define CAND_MARGIN  3.0f

// ---------------- packed fp32x2 helpers (Blackwell FFMA2) --------------------
__device__ __forceinline__ unsigned long long fma_f32x2(
    unsigned long long a, unsigned long long b, unsigned long long c)
{
    unsigned long long d;
    asm("fma.rn.f32x2 %0, %1, %2, %3;" : "=l"(d) : "l"(a), "l"(b), "l"(c));
    return d;
}
__device__ __forceinline__ unsigned long long bcast_f32x2(float a)
{
    unsigned long long d;
    asm("mov.b64 %0, {%1, %1};" : "=l"(d) : "f"(a));
    return d;
}
__device__ __forceinline__ void unpack_f32x2(unsigned long long v, float& lo, float& hi)
{
    asm("mov.b64 {%0, %1}, %2;" : "=f"(lo), "=f"(hi) : "l"(v));
}

// ---------------- scratch (static device globals: alloc-free) ----------------
__device__ float g_p[(size_t)N_ROWS * DIM_H];        // p, then (p - closest)
__device__ float g_upd[(size_t)N_ROWS * DIM_H];      // memory_update
__device__ float g_mnorm[MEM_M];                     // ||m_j||^2
__device__ int   g_idx[N_ROWS];                      // argmin indices
__device__ __nv_bfloat16 g_phi[(size_t)N_ROWS * DIM_H];  // bf16(p)
__device__ __nv_bfloat16 g_mhi[(size_t)MEM_M * DIM_H];   // bf16(memory)
__device__ __half g_scores[(size_t)N_ROWS * MEM_M];      // approx scores (256MB)

// ============ packed-fp32 micro-kernel core (proj / upd GEMMs) ===============
struct MicroAcc {
    unsigned long long acc2[8][4];
    __device__ __forceinline__ void zero() {
#pragma unroll
        for (int r = 0; r < 8; r++)
#pragma unroll
            for (int c = 0; c < 4; c++) acc2[r][c] = 0ULL;
    }
};

__device__ __forceinline__ void micro_mma_tile(
    MicroAcc& m, const float (*As)[132], const float (*Bs)[132], int ty, int tx)
{
#pragma unroll
    for (int k = 0; k < 16; k++) {
        float4 a0 = *reinterpret_cast<const float4*>(&As[k][ty * 8]);
        float4 a1 = *reinterpret_cast<const float4*>(&As[k][ty * 8 + 4]);
        ulonglong2 b01 = *reinterpret_cast<const ulonglong2*>(&Bs[k][tx * 8]);
        ulonglong2 b23 = *reinterpret_cast<const ulonglong2*>(&Bs[k][tx * 8 + 4]);
        unsigned long long bb[4] = {b01.x, b01.y, b23.x, b23.y};
        float a[8] = {a0.x, a0.y, a0.z, a0.w, a1.x, a1.y, a1.z, a1.w};
#pragma unroll
        for (int r = 0; r < 8; r++) {
            unsigned long long pa = bcast_f32x2(a[r]);
#pragma unroll
            for (int c = 0; c < 4; c++)
                m.acc2[r][c] = fma_f32x2(pa, bb[c], m.acc2[r][c]);
        }
    }
}

template<int K>
__device__ __forceinline__ void load_tiles(
    const float* __restrict__ A, const float* __restrict__ B,
    float (*As)[132], float (*Bs)[132], int i0, int j0, int k0, int tid)
{
    for (int q = tid; q < 512; q += 256) {
        int row = q >> 2;
        int k4  = (q & 3) << 2;
        float4 va = *reinterpret_cast<const float4*>(&A[(size_t)(i0 + row) * K + k0 + k4]);
        As[k4 + 0][row] = va.x; As[k4 + 1][row] = va.y;
        As[k4 + 2][row] = va.z; As[k4 + 3][row] = va.w;
        float4 vb = *reinterpret_cast<const float4*>(&B[(size_t)(j0 + row) * K + k0 + k4]);
        Bs[k4 + 0][row] = vb.x; Bs[k4 + 1][row] = vb.y;
        Bs[k4 + 2][row] = vb.z; Bs[k4 + 3][row] = vb.w;
    }
}

template<int K>
__global__ void __launch_bounds__(256)
gemm_nt_bias(const float* __restrict__ A, const float* __restrict__ B,
             const float* __restrict__ bias, float* __restrict__ C, int Hdim)
{
    __shared__ float As[16][132];
    __shared__ float Bs[16][132];
    const int i0  = blockIdx.y * 128;
    const int j0  = blockIdx.x * 128;
    const int tid = threadIdx.x;
    const int tx  = tid & 15;
    const int ty  = tid >> 4;

    MicroAcc m;
    m.zero();

    for (int k0 = 0; k0 < K; k0 += 16) {
        load_tiles<K>(A, B, As, Bs, i0, j0, k0, tid);
        __syncthreads();
        micro_mma_tile(m, As, Bs, ty, tx);
        __syncthreads();
    }

#pragma unroll
    for (int r = 0; r < 8; r++) {
        int row = i0 + ty * 8 + r;
        int col = j0 + tx * 8;
        float o[8];
#pragma unroll
        for (int c = 0; c < 4; c++)
            unpack_f32x2(m.acc2[r][c], o[2 * c], o[2 * c + 1]);
        float4 o0, o1;
        o0.x = o[0] + bias[col + 0];
        o0.y = o[1] + bias[col + 1];
        o0.z = o[2] + bias[col + 2];
        o0.w = o[3] + bias[col + 3];
        o1.x = o[4] + bias[col + 4];
        o1.y = o[5] + bias[col + 5];
        o1.z = o[6] + bias[col + 6];
        o1.w = o[7] + bias[col + 7];
        *reinterpret_cast<float4*>(&C[(size_t)row * Hdim + col])     = o0;
        *reinterpret_cast<float4*>(&C[(size_t)row * Hdim + col + 4]) = o1;
    }
}

// ---------------- memory row squared-norms -----------------------------------
__global__ void __launch_bounds__(256)
row_norms(const float* __restrict__ Mem)
{
    int row  = blockIdx.x * 8 + (threadIdx.x >> 5);
    int lane = threadIdx.x & 31;
    const float4* mrow = reinterpret_cast<const float4*>(Mem + (size_t)row * DIM_H);
    float s = 0.f;
#pragma unroll
    for (int t = lane; t < DIM_H / 4; t += 32) {
        float4 v = mrow[t];
        s += v.x * v.x + v.y * v.y + v.z * v.z + v.w * v.w;
    }
#pragma unroll
    for (int o = 16; o; o >>= 1) s += __shfl_xor_sync(0xffffffffu, s, o);
    if (lane == 0) g_mnorm[row] = s;
}

// ---------------- fp32 -> bf16 conversion -------------------------------------
__global__ void __launch_bounds__(256)
to_bf16(const float* __restrict__ src, __nv_bfloat16* __restrict__ dst)
{
    size_t e = ((size_t)blockIdx.x * 256 + threadIdx.x) * 4;   // 4 elems/thread
    float4 v = *reinterpret_cast<const float4*>(&src[e]);
    __nv_bfloat162* d2 = reinterpret_cast<__nv_bfloat162*>(&dst[e]);
    d2[0] = __floats2bfloat162_rn(v.x, v.y);
    d2[1] = __floats2bfloat162_rn(v.z, v.w);
}

// ---------------- bf16 tensor-core score GEMM ---------------------------------
// scores[i,j] = mnorm[j] - 2 * (phi_i . mhi_j) - 512   stored fp16
// block 128x128, 8 warps (2x4), warp tile 64x32, mma.sync m16n8k16 bf16
#define SSTRIDE 72   // bf16 elements per smem row (144B: conflict-free ldmatrix)

__device__ __forceinline__ uint32_t smem_u32(const void* p)
{
    return (uint32_t)__cvta_generic_to_shared(p);
}

__global__ void __launch_bounds__(256)
score_gemm(const __nv_bfloat16* __restrict__ A, const __nv_bfloat16* __restrict__ B)
{
    __shared__ __nv_bfloat16 As[128 * SSTRIDE];
    __shared__ __nv_bfloat16 Bs[128 * SSTRIDE];

    const int j0   = blockIdx.x * 128;
    const int i0   = blockIdx.y * 128;
    const int tid  = threadIdx.x;
    const int lane = tid & 31;
    const int warp = tid >> 5;
    const int wm   = warp >> 2;       // 0..1  (64-row slices)
    const int wn   = warp & 3;        // 0..3  (32-col slices)

    float c[4][4][4];
#pragma unroll
    for (int mt = 0; mt < 4; mt++)
#pragma unroll
        for (int nt = 0; nt < 4; nt++)
#pragma unroll
            for (int e = 0; e < 4; e++) c[mt][nt][e] = 0.f;

    for (int k0 = 0; k0 < DIM_H; k0 += 64) {
        // stage 128x64 bf16 tiles of A and B (16B chunks)
        for (int q = tid; q < 1024; q += 256) {
            int row = q >> 3;
            int ch  = q & 7;
            uint4 va = *reinterpret_cast<const uint4*>(&A[(size_t)(i0 + row) * DIM_H + k0 + ch * 8]);
            *reinterpret_cast<uint4*>(&As[row * SSTRIDE + ch * 8]) = va;
            uint4 vb = *reinterpret_cast<const uint4*>(&B[(size_t)(j0 + row) * DIM_H + k0 + ch * 8]);
            *reinterpret_cast<uint4*>(&Bs[row * SSTRIDE + ch * 8]) = vb;
        }
        __syncthreads();

#pragma unroll
        for (int kt = 0; kt < 4; kt++) {
            // A fragments: 4 m16 tiles
            uint32_t a[4][4];
#pragma unroll
            for (int mt = 0; mt < 4; mt++) {
                int row = wm * 64 + mt * 16 + (lane & 15);
                int col = kt * 16 + (lane >> 4) * 8;
                uint32_t addr = smem_u32(&As[row * SSTRIDE + col]);
                asm volatile("ldmatrix.sync.aligned.m8n8.x4.shared.b16 {%0,%1,%2,%3}, [%4];"
                             : "=r"(a[mt][0]), "=r"(a[mt][1]), "=r"(a[mt][2]), "=r"(a[mt][3])
                             : "r"(addr));
            }
            // B fragments: 4 n8 tiles via 2 x4 loads
            uint32_t b[4][2];
#pragma unroll
            for (int ntp = 0; ntp < 2; ntp++) {
                int n   = wn * 32 + ntp * 16 + ((lane >> 4) & 1) * 8 + (lane & 7);
                int col = kt * 16 + ((lane >> 3) & 1) * 8;
                uint32_t addr = smem_u32(&Bs[n * SSTRIDE + col]);
                uint32_t r0, r1, r2, r3;
                asm volatile("ldmatrix.sync.aligned.m8n8.x4.shared.b16 {%0,%1,%2,%3}, [%4];"
                             : "=r"(r0), "=r"(r1), "=r"(r2), "=r"(r3)
                             : "r"(addr));
                b[2 * ntp][0]     = r0; b[2 * ntp][1]     = r1;
                b[2 * ntp + 1][0] = r2; b[2 * ntp + 1][1] = r3;
            }
#pragma unroll
            for (int mt = 0; mt < 4; mt++)
#pragma unroll
                for (int nt = 0; nt < 4; nt++) {
                    asm volatile(
                        "mma.sync.aligned.m16n8k16.row.col.f32.bf16.bf16.f32 "
                        "{%0,%1,%2,%3}, {%4,%5,%6,%7}, {%8,%9}, {%0,%1,%2,%3};"
                        : "+f"(c[mt][nt][0]), "+f"(c[mt][nt][1]),
                          "+f"(c[mt][nt][2]), "+f"(c[mt][nt][3])
                        : "r"(a[mt][0]), "r"(a[mt][1]), "r"(a[mt][2]), "r"(a[mt][3]),
                          "r"(b[nt][0]), "r"(b[nt][1]));
                }
        }
        __syncthreads();
    }

    // epilogue: s = mnorm[j] - 2*dot - 512, store fp16 pairs
#pragma unroll
    for (int nt = 0; nt < 4; nt++) {
        int j = j0 + wn * 32 + nt * 8 + (lane & 3) * 2;
        float mn0 = g_mnorm[j];
        float mn1 = g_mnorm[j + 1];
#pragma unroll
        for (int mt = 0; mt < 4; mt++) {
            int i = i0 + wm * 64 + mt * 16 + (lane >> 2);
            float s00 = fmaf(-2.f, c[mt][nt][0], mn0) - SCORE_BIAS;
            float s01 = fmaf(-2.f, c[mt][nt][1], mn1) - SCORE_BIAS;
            float s10 = fmaf(-2.f, c[mt][nt][2], mn0) - SCORE_BIAS;
            float s11 = fmaf(-2.f, c[mt][nt][3], mn1) - SCORE_BIAS;
            *reinterpret_cast<__half2*>(&g_scores[(size_t)i * MEM_M + j]) =
                __floats2half2_rn(s00, s01);
            *reinterpret_cast<__half2*>(&g_scores[(size_t)(i + 8) * MEM_M + j]) =
                __floats2half2_rn(s10, s11);
        }
    }
}

// ---------------- per-row min scan + exact rescreen ----------------------------
// one warp per row; 8 warps per block
__global__ void __launch_bounds__(256)
minscan_rescreen(const float* __restrict__ Mem)
{
    __shared__ int s_cand[8][64];
    __shared__ int s_cnt[8];

    const int warp = threadIdx.x >> 5;
    const int lane = threadIdx.x & 31;
    const int row  = blockIdx.x * 8 + warp;
    if (lane == 0) s_cnt[warp] = 0;
    __syncwarp();

    const uint4* srow = reinterpret_cast<const uint4*>(&g_scores[(size_t)row * MEM_M]);

    // pass 1: approximate min
    float mn = FLT_MAX;
    for (int it = 0; it < MEM_M / 256; it++) {
        uint4 v = srow[it * 32 + lane];
        const __half2* h = reinterpret_cast<const __half2*>(&v);
#pragma unroll
        for (int e = 0; e < 4; e++) {
            float2 f = __half22float2(h[e]);
            mn = fminf(mn, fminf(f.x, f.y));
        }
    }
#pragma unroll
    for (int o = 16; o; o >>= 1) mn = fminf(mn, __shfl_xor_sync(0xffffffffu, mn, o));
    const float thr = mn + CAND_MARGIN;

    // pass 2: collect candidates below threshold
    for (int it = 0; it < MEM_M / 256; it++) {
        uint4 v = srow[it * 32 + lane];
        const __half2* h = reinterpret_cast<const __half2*>(&v);
        int jbase = (it * 32 + lane) * 8;
#pragma unroll
        for (int e = 0; e < 4; e++) {
            float2 f = __half22float2(h[e]);
            if (f.x <= thr) {
                int slot = atomicAdd(&s_cnt[warp], 1);
                if (slot < 64) s_cand[warp][slot] = jbase + 2 * e;
            }
            if (f.y <= thr) {
                int slot = atomicAdd(&s_cnt[warp], 1);
                if (slot < 64) s_cand[warp][slot] = jbase + 2 * e + 1;
            }
        }
    }
    __syncwarp();
    int cnt = min(s_cnt[warp], 64);

    // exact fp32 rescreen of candidates (warp-cooperative dots)
    const float4* prow = reinterpret_cast<const float4*>(&g_p[(size_t)row * DIM_H]);
    float best  = FLT_MAX;
    int   bestj = 0x7fffffff;
    for (int cc = 0; cc < cnt; cc++) {
        int j = s_cand[warp][cc];
        const float4* mrow = reinterpret_cast<const float4*>(&Mem[(size_t)j * DIM_H]);
        float d = 0.f;
#pragma unroll
        for (int t = 0; t < 4; t++) {
            float4 pv = prow[lane * 4 + t];
            float4 mv = mrow[lane * 4 + t];
            d += pv.x * mv.x + pv.y * mv.y + pv.z * mv.z + pv.w * mv.w;
        }
#pragma unroll
        for (int o = 16; o; o >>= 1) d += __shfl_xor_sync(0xffffffffu, d, o);
        float s = fmaf(-2.f, d, g_mnorm[j]);
        if (s < best || (s == best && j < bestj)) { best = s; bestj = j; }
    }
    if (lane == 0) g_idx[row] = bestj;
}

// ---------------- gather closest, compute (p - closest) in place --------------
__global__ void __launch_bounds__(256)
gather_sub(const float* __restrict__ Mem, float* __restrict__ closest_out)
{
    size_t e  = (size_t)blockIdx.x * 256 + threadIdx.x;   // over N*H/4
    int    i  = (int)(e >> 7);                            // H/4 = 128
    int    h4 = (int)(e & 127);
    int    j  = g_idx[i];
    float4 m  = reinterpret_cast<const float4*>(Mem)[(size_t)j * (DIM_H / 4) + h4];
    float4* P4 = reinterpret_cast<float4*>(g_p);
    float4  p  = P4[e];
    reinterpret_cast<float4*>(closest_out)[e] = m;
    p.x -= m.x; p.y -= m.y; p.z -= m.z; p.w -= m.w;
    P4[e] = p;
}

// ---------------- scatter-add updates into output memory ----------------------
__global__ void __launch_bounds__(256)
scatter_add(float* __restrict__ out2)
{
    size_t e = (size_t)blockIdx.x * 256 + threadIdx.x;    // over N*H
    int    i = (int)(e >> 9);                             // H = 512
    int    h = (int)(e & 511);
    int    j = g_idx[i];
    atomicAdd(&out2[(size_t)j * DIM_H + h], RATE * g_upd[e]);
}

// ---------------- launch -------------------------------------------------------
extern "C" void kernel_launch(void* const* d_in, const int* in_sizes, int n_in,
                              void* d_out, int out_size)
{
    const float* V   = (const float*)d_in[0];  // [N, DIM_IN]
    const float* Mem = (const float*)d_in[1];  // [M, H]
    const float* Wp  = (const float*)d_in[2];  // [H, DIM_IN]
    const float* bp  = (const float*)d_in[3];  // [H]
    const float* Wu  = (const float*)d_in[4];  // [H, H]
    const float* bu  = (const float*)d_in[5];  // [H]

    float* out         = (float*)d_out;
    float* closest_out = out;                                 // [N, H]
    float* out2        = out + (size_t)N_ROWS * DIM_H;        // [M, H]

    float* p;   cudaGetSymbolAddress((void**)&p,   g_p);
    float* upd; cudaGetSymbolAddress((void**)&upd, g_upd);
    __nv_bfloat16* phi; cudaGetSymbolAddress((void**)&phi, g_phi);
    __nv_bfloat16* mhi; cudaGetSymbolAddress((void**)&mhi, g_mhi);

    // p = V @ Wp^T + bp   (exact fp32)
    gemm_nt_bias<DIM_IN><<<dim3(DIM_H / 128, N_ROWS / 128), 256>>>(V, Wp, bp, p, DIM_H);
    // ||m_j||^2
    row_norms<<<MEM_M / 8, 256>>>(Mem);
    // bf16 copies for the tensor-core distance GEMM
    to_bf16<<<(N_ROWS * DIM_H / 4) / 256, 256>>>(p, phi);
    to_bf16<<<(MEM_M * DIM_H / 4) / 256, 256>>>(Mem, mhi);
    // approximate scores via bf16 mma.sync
    score_gemm<<<dim3(MEM_M / 128, N_ROWS / 128), 256>>>(phi, mhi);
    // per-row min + exact fp32 rescreen -> indices
    minscan_rescreen<<<N_ROWS / 8, 256>>>(Mem);
    // closest = Mem[idx]; p <- p - closest
    gather_sub<<<(N_ROWS * (DIM_H / 4)) / 256, 256>>>(Mem, closest_out);
    // upd = (p - closest) @ Wu^T + bu   (exact fp32)
    gemm_nt_bias<DIM_H><<<dim3(DIM_H / 128, N_ROWS / 128), 256>>>(p, Wu, bu, upd, DIM_H);
    // updated_memory = Mem, then scatter-add RATE*upd at idx
    cudaMemcpyAsync(out2, Mem, (size_t)MEM_M * DIM_H * sizeof(float),
                    cudaMemcpyDeviceToDevice);
    scatter_add<<<(N_ROWS * DIM_H) / 256, 256>>>(out2);
}

// round 12
// speedup vs baseline: 1.0123x; 1.0123x over previous
#include <cuda_runtime.h>
#include <cuda_bf16.h>
#include <cuda_fp16.h>
#include <cfloat>
#include <cstdint>

#define N_ROWS 16384
#define DIM_IN 1024
#define DIM_H  512
#define MEM_M  8192
#define RATE   0.5f
#define SCORE_BIAS   512.0f
#define CAND_MARGIN  3.0f

// ---------------- packed fp32x2 helpers (Blackwell FFMA2) --------------------
__device__ __forceinline__ unsigned long long fma_f32x2(
    unsigned long long a, unsigned long long b, unsigned long long c)
{
    unsigned long long d;
    asm("fma.rn.f32x2 %0, %1, %2, %3;" : "=l"(d) : "l"(a), "l"(b), "l"(c));
    return d;
}
__device__ __forceinline__ unsigned long long bcast_f32x2(float a)
{
    unsigned long long d;
    asm("mov.b64 %0, {%1, %1};" : "=l"(d) : "f"(a));
    return d;
}
__device__ __forceinline__ void unpack_f32x2(unsigned long long v, float& lo, float& hi)
{
    asm("mov.b64 {%0, %1}, %2;" : "=f"(lo), "=f"(hi) : "l"(v));
}

// ---------------- scratch (static device globals: alloc-free) ----------------
__device__ float g_p[(size_t)N_ROWS * DIM_H];        // p, then (p - closest)
__device__ float g_upd[(size_t)N_ROWS * DIM_H];      // memory_update
__device__ float g_mnorm[MEM_M];                     // ||m_j||^2
__device__ int   g_idx[N_ROWS];                      // argmin indices
__device__ __nv_bfloat16 g_phi[(size_t)N_ROWS * DIM_H];  // bf16(p)
__device__ __nv_bfloat16 g_mhi[(size_t)MEM_M * DIM_H];   // bf16(memory)
__device__ __half g_scores[(size_t)N_ROWS * MEM_M];      // approx scores (256MB)

// ============ packed-fp32 micro-kernel core (proj / upd GEMMs) ===============
struct MicroAcc {
    unsigned long long acc2[8][4];
    __device__ __forceinline__ void zero() {
#pragma unroll
        for (int r = 0; r < 8; r++)
#pragma unroll
            for (int c = 0; c < 4; c++) acc2[r][c] = 0ULL;
    }
};

__device__ __forceinline__ void micro_mma_tile(
    MicroAcc& m, const float (*As)[132], const float (*Bs)[132], int ty, int tx)
{
#pragma unroll
    for (int k = 0; k < 16; k++) {
        float4 a0 = *reinterpret_cast<const float4*>(&As[k][ty * 8]);
        float4 a1 = *reinterpret_cast<const float4*>(&As[k][ty * 8 + 4]);
        ulonglong2 b01 = *reinterpret_cast<const ulonglong2*>(&Bs[k][tx * 8]);
        ulonglong2 b23 = *reinterpret_cast<const ulonglong2*>(&Bs[k][tx * 8 + 4]);
        unsigned long long bb[4] = {b01.x, b01.y, b23.x, b23.y};
        float a[8] = {a0.x, a0.y, a0.z, a0.w, a1.x, a1.y, a1.z, a1.w};
#pragma unroll
        for (int r = 0; r < 8; r++) {
            unsigned long long pa = bcast_f32x2(a[r]);
#pragma unroll
            for (int c = 0; c < 4; c++)
                m.acc2[r][c] = fma_f32x2(pa, bb[c], m.acc2[r][c]);
        }
    }
}

template<int K>
__device__ __forceinline__ void load_tiles(
    const float* __restrict__ A, const float* __restrict__ B,
    float (*As)[132], float (*Bs)[132], int i0, int j0, int k0, int tid)
{
    for (int q = tid; q < 512; q += 256) {
        int row = q >> 2;
        int k4  = (q & 3) << 2;
        float4 va = *reinterpret_cast<const float4*>(&A[(size_t)(i0 + row) * K + k0 + k4]);
        As[k4 + 0][row] = va.x; As[k4 + 1][row] = va.y;
        As[k4 + 2][row] = va.z; As[k4 + 3][row] = va.w;
        float4 vb = *reinterpret_cast<const float4*>(&B[(size_t)(j0 + row) * K + k0 + k4]);
        Bs[k4 + 0][row] = vb.x; Bs[k4 + 1][row] = vb.y;
        Bs[k4 + 2][row] = vb.z; Bs[k4 + 3][row] = vb.w;
    }
}

template<int K>
__global__ void __launch_bounds__(256)
gemm_nt_bias(const float* __restrict__ A, const float* __restrict__ B,
             const float* __restrict__ bias, float* __restrict__ C, int Hdim)
{
    __shared__ float As[16][132];
    __shared__ float Bs[16][132];
    const int i0  = blockIdx.y * 128;
    const int j0  = blockIdx.x * 128;
    const int tid = threadIdx.x;
    const int tx  = tid & 15;
    const int ty  = tid >> 4;

    MicroAcc m;
    m.zero();

    for (int k0 = 0; k0 < K; k0 += 16) {
        load_tiles<K>(A, B, As, Bs, i0, j0, k0, tid);
        __syncthreads();
        micro_mma_tile(m, As, Bs, ty, tx);
        __syncthreads();
    }

#pragma unroll
    for (int r = 0; r < 8; r++) {
        int row = i0 + ty * 8 + r;
        int col = j0 + tx * 8;
        float o[8];
#pragma unroll
        for (int c = 0; c < 4; c++)
            unpack_f32x2(m.acc2[r][c], o[2 * c], o[2 * c + 1]);
        float4 o0, o1;
        o0.x = o[0] + bias[col + 0];
        o0.y = o[1] + bias[col + 1];
        o0.z = o[2] + bias[col + 2];
        o0.w = o[3] + bias[col + 3];
        o1.x = o[4] + bias[col + 4];
        o1.y = o[5] + bias[col + 5];
        o1.z = o[6] + bias[col + 6];
        o1.w = o[7] + bias[col + 7];
        *reinterpret_cast<float4*>(&C[(size_t)row * Hdim + col])     = o0;
        *reinterpret_cast<float4*>(&C[(size_t)row * Hdim + col + 4]) = o1;
    }
}

// ---------------- memory row squared-norms -----------------------------------
__global__ void __launch_bounds__(256)
row_norms(const float* __restrict__ Mem)
{
    int row  = blockIdx.x * 8 + (threadIdx.x >> 5);
    int lane = threadIdx.x & 31;
    const float4* mrow = reinterpret_cast<const float4*>(Mem + (size_t)row * DIM_H);
    float s = 0.f;
#pragma unroll
    for (int t = lane; t < DIM_H / 4; t += 32) {
        float4 v = mrow[t];
        s += v.x * v.x + v.y * v.y + v.z * v.z + v.w * v.w;
    }
#pragma unroll
    for (int o = 16; o; o >>= 1) s += __shfl_xor_sync(0xffffffffu, s, o);
    if (lane == 0) g_mnorm[row] = s;
}

// ---------------- fp32 -> bf16 conversion -------------------------------------
__global__ void __launch_bounds__(256)
to_bf16(const float* __restrict__ src, __nv_bfloat16* __restrict__ dst)
{
    size_t e = ((size_t)blockIdx.x * 256 + threadIdx.x) * 4;   // 4 elems/thread
    float4 v = *reinterpret_cast<const float4*>(&src[e]);
    __nv_bfloat162* d2 = reinterpret_cast<__nv_bfloat162*>(&dst[e]);
    d2[0] = __floats2bfloat162_rn(v.x, v.y);
    d2[1] = __floats2bfloat162_rn(v.z, v.w);
}

// ---------------- bf16 tensor-core score GEMM ---------------------------------
// scores[i,j] = mnorm[j] - 2 * (phi_i . mhi_j) - 512   stored fp16
// block 128x128, 8 warps (2x4), warp tile 64x32, mma.sync m16n8k16 bf16
#define SSTRIDE 72   // bf16 elements per smem row (144B: conflict-free ldmatrix)

__device__ __forceinline__ uint32_t smem_u32(const void* p)
{
    return (uint32_t)__cvta_generic_to_shared(p);
}

__global__ void __launch_bounds__(256)
score_gemm(const __nv_bfloat16* __restrict__ A, const __nv_bfloat16* __restrict__ B)
{
    __shared__ __nv_bfloat16 As[128 * SSTRIDE];
    __shared__ __nv_bfloat16 Bs[128 * SSTRIDE];

    const int j0   = blockIdx.x * 128;
    const int i0   = blockIdx.y * 128;
    const int tid  = threadIdx.x;
    const int lane = tid & 31;
    const int warp = tid >> 5;
    const int wm   = warp >> 2;       // 0..1  (64-row slices)
    const int wn   = warp & 3;        // 0..3  (32-col slices)

    float c[4][4][4];
#pragma unroll
    for (int mt = 0; mt < 4; mt++)
#pragma unroll
        for (int nt = 0; nt < 4; nt++)
#pragma unroll
            for (int e = 0; e < 4; e++) c[mt][nt][e] = 0.f;

    for (int k0 = 0; k0 < DIM_H; k0 += 64) {
        // stage 128x64 bf16 tiles of A and B (16B chunks)
        for (int q = tid; q < 1024; q += 256) {
            int row = q >> 3;
            int ch  = q & 7;
            uint4 va = *reinterpret_cast<const uint4*>(&A[(size_t)(i0 + row) * DIM_H + k0 + ch * 8]);
            *reinterpret_cast<uint4*>(&As[row * SSTRIDE + ch * 8]) = va;
            uint4 vb = *reinterpret_cast<const uint4*>(&B[(size_t)(j0 + row) * DIM_H + k0 + ch * 8]);
            *reinterpret_cast<uint4*>(&Bs[row * SSTRIDE + ch * 8]) = vb;
        }
        __syncthreads();

#pragma unroll
        for (int kt = 0; kt < 4; kt++) {
            // A fragments: 4 m16 tiles
            uint32_t a[4][4];
#pragma unroll
            for (int mt = 0; mt < 4; mt++) {
                int row = wm * 64 + mt * 16 + (lane & 15);
                int col = kt * 16 + (lane >> 4) * 8;
                uint32_t addr = smem_u32(&As[row * SSTRIDE + col]);
                asm volatile("ldmatrix.sync.aligned.m8n8.x4.shared.b16 {%0,%1,%2,%3}, [%4];"
                             : "=r"(a[mt][0]), "=r"(a[mt][1]), "=r"(a[mt][2]), "=r"(a[mt][3])
                             : "r"(addr));
            }
            // B fragments: 4 n8 tiles via 2 x4 loads
            uint32_t b[4][2];
#pragma unroll
            for (int ntp = 0; ntp < 2; ntp++) {
                int n   = wn * 32 + ntp * 16 + ((lane >> 4) & 1) * 8 + (lane & 7);
                int col = kt * 16 + ((lane >> 3) & 1) * 8;
                uint32_t addr = smem_u32(&Bs[n * SSTRIDE + col]);
                uint32_t r0, r1, r2, r3;
                asm volatile("ldmatrix.sync.aligned.m8n8.x4.shared.b16 {%0,%1,%2,%3}, [%4];"
                             : "=r"(r0), "=r"(r1), "=r"(r2), "=r"(r3)
                             : "r"(addr));
                b[2 * ntp][0]     = r0; b[2 * ntp][1]     = r1;
                b[2 * ntp + 1][0] = r2; b[2 * ntp + 1][1] = r3;
            }
#pragma unroll
            for (int mt = 0; mt < 4; mt++)
#pragma unroll
                for (int nt = 0; nt < 4; nt++) {
                    asm volatile(
                        "mma.sync.aligned.m16n8k16.row.col.f32.bf16.bf16.f32 "
                        "{%0,%1,%2,%3}, {%4,%5,%6,%7}, {%8,%9}, {%0,%1,%2,%3};"
                        : "+f"(c[mt][nt][0]), "+f"(c[mt][nt][1]),
                          "+f"(c[mt][nt][2]), "+f"(c[mt][nt][3])
                        : "r"(a[mt][0]), "r"(a[mt][1]), "r"(a[mt][2]), "r"(a[mt][3]),
                          "r"(b[nt][0]), "r"(b[nt][1]));
                }
        }
        __syncthreads();
    }

    // epilogue: s = mnorm[j] - 2*dot - 512, store fp16 pairs
#pragma unroll
    for (int nt = 0; nt < 4; nt++) {
        int j = j0 + wn * 32 + nt * 8 + (lane & 3) * 2;
        float mn0 = g_mnorm[j];
        float mn1 = g_mnorm[j + 1];
#pragma unroll
        for (int mt = 0; mt < 4; mt++) {
            int i = i0 + wm * 64 + mt * 16 + (lane >> 2);
            float s00 = fmaf(-2.f, c[mt][nt][0], mn0) - SCORE_BIAS;
            float s01 = fmaf(-2.f, c[mt][nt][1], mn1) - SCORE_BIAS;
            float s10 = fmaf(-2.f, c[mt][nt][2], mn0) - SCORE_BIAS;
            float s11 = fmaf(-2.f, c[mt][nt][3], mn1) - SCORE_BIAS;
            *reinterpret_cast<__half2*>(&g_scores[(size_t)i * MEM_M + j]) =
                __floats2half2_rn(s00, s01);
            *reinterpret_cast<__half2*>(&g_scores[(size_t)(i + 8) * MEM_M + j]) =
                __floats2half2_rn(s10, s11);
        }
    }
}

// ---------------- per-row min scan + exact rescreen ----------------------------
// one warp per row; 8 warps per block
__global__ void __launch_bounds__(256)
minscan_rescreen(const float* __restrict__ Mem)
{
    __shared__ int s_cand[8][64];
    __shared__ int s_cnt[8];

    const int warp = threadIdx.x >> 5;
    const int lane = threadIdx.x & 31;
    const int row  = blockIdx.x * 8 + warp;
    if (lane == 0) s_cnt[warp] = 0;
    __syncwarp();

    const uint4* srow = reinterpret_cast<const uint4*>(&g_scores[(size_t)row * MEM_M]);

    // pass 1: approximate min
    float mn = FLT_MAX;
    for (int it = 0; it < MEM_M / 256; it++) {
        uint4 v = srow[it * 32 + lane];
        const __half2* h = reinterpret_cast<const __half2*>(&v);
#pragma unroll
        for (int e = 0; e < 4; e++) {
            float2 f = __half22float2(h[e]);
            mn = fminf(mn, fminf(f.x, f.y));
        }
    }
#pragma unroll
    for (int o = 16; o; o >>= 1) mn = fminf(mn, __shfl_xor_sync(0xffffffffu, mn, o));
    const float thr = mn + CAND_MARGIN;

    // pass 2: collect candidates below threshold
    for (int it = 0; it < MEM_M / 256; it++) {
        uint4 v = srow[it * 32 + lane];
        const __half2* h = reinterpret_cast<const __half2*>(&v);
        int jbase = (it * 32 + lane) * 8;
#pragma unroll
        for (int e = 0; e < 4; e++) {
            float2 f = __half22float2(h[e]);
            if (f.x <= thr) {
                int slot = atomicAdd(&s_cnt[warp], 1);
                if (slot < 64) s_cand[warp][slot] = jbase + 2 * e;
            }
            if (f.y <= thr) {
                int slot = atomicAdd(&s_cnt[warp], 1);
                if (slot < 64) s_cand[warp][slot] = jbase + 2 * e + 1;
            }
        }
    }
    __syncwarp();
    int cnt = min(s_cnt[warp], 64);

    // exact fp32 rescreen of candidates (warp-cooperative dots)
    const float4* prow = reinterpret_cast<const float4*>(&g_p[(size_t)row * DIM_H]);
    float best  = FLT_MAX;
    int   bestj = 0x7fffffff;
    for (int cc = 0; cc < cnt; cc++) {
        int j = s_cand[warp][cc];
        const float4* mrow = reinterpret_cast<const float4*>(&Mem[(size_t)j * DIM_H]);
        float d = 0.f;
#pragma unroll
        for (int t = 0; t < 4; t++) {
            float4 pv = prow[lane * 4 + t];
            float4 mv = mrow[lane * 4 + t];
            d += pv.x * mv.x + pv.y * mv.y + pv.z * mv.z + pv.w * mv.w;
        }
#pragma unroll
        for (int o = 16; o; o >>= 1) d += __shfl_xor_sync(0xffffffffu, d, o);
        float s = fmaf(-2.f, d, g_mnorm[j]);
        if (s < best || (s == best && j < bestj)) { best = s; bestj = j; }
    }
    if (lane == 0) g_idx[row] = bestj;
}

// ---------------- gather closest, compute (p - closest) in place --------------
__global__ void __launch_bounds__(256)
gather_sub(const float* __restrict__ Mem, float* __restrict__ closest_out)
{
    size_t e  = (size_t)blockIdx.x * 256 + threadIdx.x;   // over N*H/4
    int    i  = (int)(e >> 7);                            // H/4 = 128
    int    h4 = (int)(e & 127);
    int    j  = g_idx[i];
    float4 m  = reinterpret_cast<const float4*>(Mem)[(size_t)j * (DIM_H / 4) + h4];
    float4* P4 = reinterpret_cast<float4*>(g_p);
    float4  p  = P4[e];
    reinterpret_cast<float4*>(closest_out)[e] = m;
    p.x -= m.x; p.y -= m.y; p.z -= m.z; p.w -= m.w;
    P4[e] = p;
}

// ---------------- scatter-add updates into output memory ----------------------
__global__ void __launch_bounds__(256)
scatter_add(float* __restrict__ out2)
{
    size_t e = (size_t)blockIdx.x * 256 + threadIdx.x;    // over N*H
    int    i = (int)(e >> 9);                             // H = 512
    int    h = (int)(e & 511);
    int    j = g_idx[i];
    atomicAdd(&out2[(size_t)j * DIM_H + h], RATE * g_upd[e]);
}

// ---------------- launch -------------------------------------------------------
extern "C" void kernel_launch(void* const* d_in, const int* in_sizes, int n_in,
                              void* d_out, int out_size)
{
    const float* V   = (const float*)d_in[0];  // [N, DIM_IN]
    const float* Mem = (const float*)d_in[1];  // [M, H]
    const float* Wp  = (const float*)d_in[2];  // [H, DIM_IN]
    const float* bp  = (const float*)d_in[3];  // [H]
    const float* Wu  = (const float*)d_in[4];  // [H, H]
    const float* bu  = (const float*)d_in[5];  // [H]

    float* out         = (float*)d_out;
    float* closest_out = out;                                 // [N, H]
    float* out2        = out + (size_t)N_ROWS * DIM_H;        // [M, H]

    float* p;   cudaGetSymbolAddress((void**)&p,   g_p);
    float* upd; cudaGetSymbolAddress((void**)&upd, g_upd);
    __nv_bfloat16* phi; cudaGetSymbolAddress((void**)&phi, g_phi);
    __nv_bfloat16* mhi; cudaGetSymbolAddress((void**)&mhi, g_mhi);

    // p = V @ Wp^T + bp   (exact fp32)
    gemm_nt_bias<DIM_IN><<<dim3(DIM_H / 128, N_ROWS / 128), 256>>>(V, Wp, bp, p, DIM_H);
    // ||m_j||^2
    row_norms<<<MEM_M / 8, 256>>>(Mem);
    // bf16 copies for the tensor-core distance GEMM
    to_bf16<<<(N_ROWS * DIM_H / 4) / 256, 256>>>(p, phi);
    to_bf16<<<(MEM_M * DIM_H / 4) / 256, 256>>>(Mem, mhi);
    // approximate scores via bf16 mma.sync
    score_gemm<<<dim3(MEM_M / 128, N_ROWS / 128), 256>>>(phi, mhi);
    // per-row min + exact fp32 rescreen -> indices
    minscan_rescreen<<<N_ROWS / 8, 256>>>(Mem);
    // closest = Mem[idx]; p <- p - closest
    gather_sub<<<(N_ROWS * (DIM_H / 4)) / 256, 256>>>(Mem, closest_out);
    // upd = (p - closest) @ Wu^T + bu   (exact fp32)
    gemm_nt_bias<DIM_H><<<dim3(DIM_H / 128, N_ROWS / 128), 256>>>(p, Wu, bu, upd, DIM_H);
    // updated_memory = Mem, then scatter-add RATE*upd at idx
    cudaMemcpyAsync(out2, Mem, (size_t)MEM_M * DIM_H * sizeof(float),
                    cudaMemcpyDeviceToDevice);
    scatter_add<<<(N_ROWS * DIM_H) / 256, 256>>>(out2);
}